// round 3
// baseline (speedup 1.0000x reference)
#include <cuda_runtime.h>

// Problem dims
#define BDIM 8
#define MDIM 4
#define TLEN 2048
#define EDIM 768
#define PDIM 256
#define KDIM 64
#define VDIM 64
#define HDIM 128
#define GDIM 384   /* 3*H */
#define CDIM 384   /* P + H */
#define HIDD 192
#define NEXPD 16
#define NTOK (BDIM*MDIM*TLEN)   /* 65536 */
#define NSEQ (BDIM*MDIM)        /* 32 */

// ---------------- scratch (device globals; no allocation allowed) ----------------
__device__ float g_proc[(size_t)NTOK * PDIM];   // 64 MB: relu(te @ tp_w^T + b)
__device__ float g_rs[(size_t)NTOK * 2];        // (rbar, sbar) per token
__device__ float g_rus[(size_t)NTOK * HDIM];    // GRU outputs
__device__ float g_hid[(size_t)NTOK * HIDD];    // MLP hidden
__device__ float g_pa[PDIM], g_pb[PDIM], g_pc[PDIM];
__device__ float g_wu[GDIM], g_wr[GDIM], g_wsv[GDIM], g_w0[GDIM];
__device__ float g_cabc[3];

__constant__ int c_others[4][3] = {{1,2,3},{0,2,3},{0,1,3},{0,1,2}};

// ---------------- f32x2 packed-FMA helpers (sm_100+/sm_103a) ----------------
__device__ __forceinline__ unsigned long long pack2(float lo, float hi) {
    unsigned long long r;
    asm("mov.b64 %0, {%1, %2};" : "=l"(r) : "f"(lo), "f"(hi));
    return r;
}
__device__ __forceinline__ float2 unpack2(unsigned long long v) {
    float2 r;
    asm("mov.b64 {%0, %1}, %2;" : "=f"(r.x), "=f"(r.y) : "l"(v));
    return r;
}
__device__ __forceinline__ void fma2(unsigned long long& d, unsigned long long a, unsigned long long b) {
    asm("fma.rn.f32x2 %0, %1, %2, %0;" : "+l"(d) : "l"(a), "l"(b));
}

__device__ __forceinline__ float sigmoidf_(float x) { return 1.f / (1.f + __expf(-x)); }
__device__ __forceinline__ float tanhf_(float x)    { return 1.f - 2.f / (__expf(2.f * x) + 1.f); }

// ---------------- precompute folded small weights ----------------
__global__ void k_pre(const float* __restrict__ qw, const float* __restrict__ qb,
                      const float* __restrict__ kw, const float* __restrict__ kb,
                      const float* __restrict__ vw, const float* __restrict__ vb,
                      const float* __restrict__ wih, const float* __restrict__ bih) {
    int j = threadIdx.x;
    if (j < PDIM) {
        float a = 0.f, b = 0.f, c = 0.f;
        for (int k = 0; k < KDIM; k++) {
            float q = qw[k * PDIM + j];
            a = fmaf(q, kw[2 * k], a);
            b = fmaf(q, kw[2 * k + 1], b);
            c = fmaf(q, kb[k], c);
        }
        g_pa[j] = a; g_pb[j] = b; g_pc[j] = c;
    }
    if (j < GDIM) {
        float wr = 0.f, ws = 0.f, w0 = 0.f;
        for (int v = 0; v < VDIM; v++) {
            float w = wih[j * (1 + VDIM) + 1 + v];
            wr = fmaf(w, vw[2 * v], wr);
            ws = fmaf(w, vw[2 * v + 1], ws);
            w0 = fmaf(w, vb[v], w0);
        }
        g_wu[j] = wih[j * (1 + VDIM)];
        g_wr[j] = wr; g_wsv[j] = ws; g_w0[j] = w0 + bih[j];
    }
    if (j == 0) {
        float a = 0.f, b = 0.f, c = 0.f;
        for (int k = 0; k < KDIM; k++) {
            a = fmaf(qb[k], kw[2 * k], a);
            b = fmaf(qb[k], kw[2 * k + 1], b);
            c = fmaf(qb[k], kb[k], c);
        }
        g_cabc[0] = a; g_cabc[1] = b; g_cabc[2] = c;
    }
}

// ---------------- GEMM1: g_proc = relu(te[NTOK,768] @ tp_w[256,768]^T + b) ----------------
// Tile 128x128x16, 256 threads, 8x8 microtile via f32x2.
__global__ __launch_bounds__(256, 2) void k_gemm1(const float* __restrict__ A,
                                                  const float* __restrict__ W,
                                                  const float* __restrict__ bias) {
    __shared__ float As[16][132];
    __shared__ float Ws[16][132];
    const int bi = blockIdx.x, bj = blockIdx.y;
    const int tid = threadIdx.x;
    const int tx = tid & 15, ty = tid >> 4;
    const int row0 = bi * 128, col0 = bj * 128;

    unsigned long long acc[8][4];
#pragma unroll
    for (int i = 0; i < 8; i++)
#pragma unroll
        for (int j = 0; j < 4; j++) acc[i][j] = 0ull;

    for (int ks = 0; ks < EDIM / 16; ks++) {
#pragma unroll
        for (int p = 0; p < 2; p++) {
            int idx = tid + p * 256;
            int r = idx >> 2;
            int kq = (idx & 3) << 2;
            float4 av = *(const float4*)&A[(size_t)(row0 + r) * EDIM + ks * 16 + kq];
            As[kq + 0][r] = av.x; As[kq + 1][r] = av.y; As[kq + 2][r] = av.z; As[kq + 3][r] = av.w;
            float4 wv = *(const float4*)&W[(size_t)(col0 + r) * EDIM + ks * 16 + kq];
            Ws[kq + 0][r] = wv.x; Ws[kq + 1][r] = wv.y; Ws[kq + 2][r] = wv.z; Ws[kq + 3][r] = wv.w;
        }
        __syncthreads();
#pragma unroll
        for (int kk = 0; kk < 16; kk++) {
            float4 a0 = *(const float4*)&As[kk][ty * 8];
            float4 a1 = *(const float4*)&As[kk][ty * 8 + 4];
            ulonglong2 wv0 = *(const ulonglong2*)&Ws[kk][tx * 8];
            ulonglong2 wv1 = *(const ulonglong2*)&Ws[kk][tx * 8 + 4];
            float ar[8] = {a0.x, a0.y, a0.z, a0.w, a1.x, a1.y, a1.z, a1.w};
#pragma unroll
            for (int i = 0; i < 8; i++) {
                unsigned long long ad = pack2(ar[i], ar[i]);
                fma2(acc[i][0], ad, wv0.x);
                fma2(acc[i][1], ad, wv0.y);
                fma2(acc[i][2], ad, wv1.x);
                fma2(acc[i][3], ad, wv1.y);
            }
        }
        __syncthreads();
    }
    const int crow = row0 + ty * 8;
    const int ccol = col0 + tx * 8;
    float bb[8];
#pragma unroll
    for (int j = 0; j < 8; j++) bb[j] = bias[ccol + j];
#pragma unroll
    for (int i = 0; i < 8; i++) {
        float2 p0 = unpack2(acc[i][0]), p1 = unpack2(acc[i][1]);
        float2 p2 = unpack2(acc[i][2]), p3 = unpack2(acc[i][3]);
        float4 v0 = make_float4(fmaxf(p0.x + bb[0], 0.f), fmaxf(p0.y + bb[1], 0.f),
                                fmaxf(p1.x + bb[2], 0.f), fmaxf(p1.y + bb[3], 0.f));
        float4 v1 = make_float4(fmaxf(p2.x + bb[4], 0.f), fmaxf(p2.y + bb[5], 0.f),
                                fmaxf(p3.x + bb[6], 0.f), fmaxf(p3.y + bb[7], 0.f));
        *(float4*)&g_proc[(size_t)(crow + i) * PDIM + ccol]     = v0;
        *(float4*)&g_proc[(size_t)(crow + i) * PDIM + ccol + 4] = v1;
    }
}

// ---------------- attention scalars: per token -> (rbar, sbar) ----------------
// warp per token; 8 warps per block.
__global__ __launch_bounds__(256) void k_attn(const float* __restrict__ R, const float* __restrict__ S) {
    __shared__ float spa[PDIM], spb[PDIM], spc[PDIM];
    int tid = threadIdx.x;
    if (tid < PDIM) { spa[tid] = g_pa[tid]; spb[tid] = g_pb[tid]; spc[tid] = g_pc[tid]; }
    __syncthreads();
    int warp = tid >> 5, lane = tid & 31;
    size_t i = (size_t)blockIdx.x * 8 + warp;
    const float* pr = &g_proc[i * PDIM];
    float a = 0.f, b = 0.f, c = 0.f;
#pragma unroll
    for (int q = 0; q < 8; q++) {
        int p = lane + 32 * q;
        float x = pr[p];
        a = fmaf(x, spa[p], a);
        b = fmaf(x, spb[p], b);
        c = fmaf(x, spc[p], c);
    }
#pragma unroll
    for (int d = 16; d > 0; d >>= 1) {
        a += __shfl_xor_sync(0xffffffffu, a, d);
        b += __shfl_xor_sync(0xffffffffu, b, d);
        c += __shfl_xor_sync(0xffffffffu, c, d);
    }
    if (lane == 0) {
        a += g_cabc[0]; b += g_cabc[1]; c += g_cabc[2];
        int t = (int)(i & (TLEN - 1));
        int bm = (int)(i >> 11);
        int m = bm & 3, bb = bm >> 2;
        float r[3], s[3], sc[3];
#pragma unroll
        for (int n = 0; n < 3; n++) {
            int o = c_others[m][n];
            size_t off = (((size_t)bb * 4 + m) * 4 + o) * TLEN + t;
            r[n] = R[off]; s[n] = S[off];
            sc[n] = (fmaf(a, r[n], fmaf(b, s[n], c))) * 0.125f;
        }
        float mx = fmaxf(sc[0], fmaxf(sc[1], sc[2]));
        float e0 = __expf(sc[0] - mx), e1 = __expf(sc[1] - mx), e2 = __expf(sc[2] - mx);
        float inv = __fdividef(1.f, e0 + e1 + e2);
        float rb = (e0 * r[0] + e1 * r[1] + e2 * r[2]) * inv;
        float sb = (e0 * s[0] + e1 * s[1] + e2 * s[2]) * inv;
        g_rs[i * 2 + 0] = rb;
        g_rs[i * 2 + 1] = sb;
    }
}

// ---------------- GRU: 32 CTAs (one per sequence), w_hh rows in registers ----------------
__global__ __launch_bounds__(GDIM, 1) void k_gru(const float* __restrict__ U,
                                                 const float* __restrict__ whh,
                                                 const float* __restrict__ bhh) {
    __shared__ float sh_h[HDIM];
    __shared__ float sh_g[2 * HDIM];
    __shared__ float sh_xn[HDIM];
    __shared__ float sh_hn[HDIM];
    __shared__ float sh_sc[2][3];
    const int j = threadIdx.x;
    const int s = blockIdx.x;

    // pack this row's w_hh into 64 f32x2 registers
    unsigned long long w2[64];
    {
        const float4* wrow = (const float4*)(whh + (size_t)j * HDIM);
#pragma unroll
        for (int q = 0; q < 32; q++) {
            float4 f = wrow[q];
            w2[2 * q]     = pack2(f.x, f.y);
            w2[2 * q + 1] = pack2(f.z, f.w);
        }
    }
    const float wu = g_wu[j], wr = g_wr[j], wsx = g_wsv[j], w0 = g_w0[j];
    const float bh = bhh[j];
    float hold = 0.f;
    if (j < HDIM) sh_h[j] = 0.f;
    if (j < 3) {
        sh_sc[0][j] = (j == 0) ? U[(size_t)s * TLEN]
                               : g_rs[((size_t)s * TLEN) * 2 + (j - 1)];
    }
    __syncthreads();
    const ulonglong2* sh_h2 = (const ulonglong2*)sh_h;

    for (int t = 0; t < TLEN; t++) {
        float u = sh_sc[t & 1][0], rb = sh_sc[t & 1][1], sb = sh_sc[t & 1][2];
        float xp = fmaf(u, wu, fmaf(rb, wr, fmaf(sb, wsx, w0)));
        unsigned long long acc0 = 0ull, acc1 = 0ull;
#pragma unroll
        for (int q = 0; q < 32; q++) {
            ulonglong2 hv = sh_h2[q];
            fma2(acc0, w2[2 * q], hv.x);
            fma2(acc1, w2[2 * q + 1], hv.y);
        }
        float2 fa = unpack2(acc0), fb = unpack2(acc1);
        float hp = bh + ((fa.x + fa.y) + (fb.x + fb.y));
        if (j < 2 * HDIM) sh_g[j] = xp + hp;
        else { sh_xn[j - 2 * HDIM] = xp; sh_hn[j - 2 * HDIM] = hp; }
        // prefetch next step scalars (threads 381..383)
        if (j >= GDIM - 3 && t + 1 < TLEN) {
            int q = j - (GDIM - 3);
            size_t nxt = (size_t)s * TLEN + (t + 1);
            sh_sc[(t + 1) & 1][q] = (q == 0) ? U[nxt] : g_rs[nxt * 2 + (q - 1)];
        }
        __syncthreads();
        if (j < HDIM) {
            float r = sigmoidf_(sh_g[j]);
            float z = sigmoidf_(sh_g[HDIM + j]);
            float n = tanhf_(fmaf(r, sh_hn[j], sh_xn[j]));
            hold = fmaf(z, hold - n, n);   // (1-z)*n + z*h
            sh_h[j] = hold;
            g_rus[((size_t)s * TLEN + t) * HDIM + j] = hold;
        }
        __syncthreads();
    }
}

// ---------------- MLP1: g_hid = relu([proc|rus][NTOK,384] @ w1[192,384]^T + b1) ----------------
// Tile 128x96x16, 256 threads, 8x6 microtile via f32x2. grid.y = 2.
__global__ __launch_bounds__(256, 2) void k_mlp1(const float* __restrict__ W,
                                                 const float* __restrict__ bias) {
    __shared__ float As[16][132];
    __shared__ float Ws[16][100];
    const int bi = blockIdx.x, bj = blockIdx.y;
    const int tid = threadIdx.x;
    const int tx = tid & 15, ty = tid >> 4;
    const int row0 = bi * 128, col0 = bj * 96;

    unsigned long long acc[8][3];
#pragma unroll
    for (int i = 0; i < 8; i++)
#pragma unroll
        for (int j = 0; j < 3; j++) acc[i][j] = 0ull;

    for (int ks = 0; ks < CDIM / 16; ks++) {
#pragma unroll
        for (int p = 0; p < 2; p++) {
            int idx = tid + p * 256;
            int r = idx >> 2;
            int kq = (idx & 3) << 2;
            int k = ks * 16 + kq;
            float4 av;
            if (k < PDIM) av = *(const float4*)&g_proc[(size_t)(row0 + r) * PDIM + k];
            else          av = *(const float4*)&g_rus[(size_t)(row0 + r) * HDIM + (k - PDIM)];
            As[kq + 0][r] = av.x; As[kq + 1][r] = av.y; As[kq + 2][r] = av.z; As[kq + 3][r] = av.w;
        }
#pragma unroll
        for (int p = 0; p < 2; p++) {
            int idx = tid + p * 256;
            if (idx < 384) {
                int r = idx >> 2;
                int kq = (idx & 3) << 2;
                float4 wv = *(const float4*)&W[(size_t)(col0 + r) * CDIM + ks * 16 + kq];
                Ws[kq + 0][r] = wv.x; Ws[kq + 1][r] = wv.y; Ws[kq + 2][r] = wv.z; Ws[kq + 3][r] = wv.w;
            }
        }
        __syncthreads();
#pragma unroll
        for (int kk = 0; kk < 16; kk++) {
            float4 a0 = *(const float4*)&As[kk][ty * 8];
            float4 a1 = *(const float4*)&As[kk][ty * 8 + 4];
            const unsigned long long* wp = (const unsigned long long*)&Ws[kk][tx * 6];
            unsigned long long wv0 = wp[0], wv1 = wp[1], wv2 = wp[2];
            float ar[8] = {a0.x, a0.y, a0.z, a0.w, a1.x, a1.y, a1.z, a1.w};
#pragma unroll
            for (int i = 0; i < 8; i++) {
                unsigned long long ad = pack2(ar[i], ar[i]);
                fma2(acc[i][0], ad, wv0);
                fma2(acc[i][1], ad, wv1);
                fma2(acc[i][2], ad, wv2);
            }
        }
        __syncthreads();
    }
    const int crow = row0 + ty * 8;
    const int ccol = col0 + tx * 6;
    float bb[6];
#pragma unroll
    for (int j = 0; j < 6; j++) bb[j] = bias[ccol + j];
#pragma unroll
    for (int i = 0; i < 8; i++) {
        float2 p0 = unpack2(acc[i][0]), p1 = unpack2(acc[i][1]), p2 = unpack2(acc[i][2]);
        float2 v0 = make_float2(fmaxf(p0.x + bb[0], 0.f), fmaxf(p0.y + bb[1], 0.f));
        float2 v1 = make_float2(fmaxf(p1.x + bb[2], 0.f), fmaxf(p1.y + bb[3], 0.f));
        float2 v2 = make_float2(fmaxf(p2.x + bb[4], 0.f), fmaxf(p2.y + bb[5], 0.f));
        size_t base = (size_t)(crow + i) * HIDD + ccol;
        *(float2*)&g_hid[base]     = v0;
        *(float2*)&g_hid[base + 2] = v1;
        *(float2*)&g_hid[base + 4] = v2;
    }
}

// ---------------- logits: out = g_hid @ w2[16,192]^T + b2 ----------------
__global__ __launch_bounds__(256) void k_logits(const float* __restrict__ w2,
                                                const float* __restrict__ b2,
                                                float* __restrict__ out) {
    __shared__ float sw[NEXPD * HIDD];
    __shared__ float sb[NEXPD];
    int tid = threadIdx.x;
    for (int idx = tid; idx < NEXPD * HIDD; idx += 256) sw[idx] = w2[idx];
    if (tid < NEXPD) sb[tid] = b2[tid];
    __syncthreads();
    int warp = tid >> 5, lane = tid & 31;
    size_t i = (size_t)blockIdx.x * 8 + warp;
    float h[6];
#pragma unroll
    for (int q = 0; q < 6; q++) h[q] = g_hid[i * HIDD + lane + 32 * q];
    float res = 0.f;
#pragma unroll
    for (int o = 0; o < NEXPD; o++) {
        float p = 0.f;
#pragma unroll
        for (int q = 0; q < 6; q++) p = fmaf(h[q], sw[o * HIDD + lane + 32 * q], p);
#pragma unroll
        for (int d = 16; d > 0; d >>= 1) p += __shfl_xor_sync(0xffffffffu, p, d);
        if (lane == o) res = p + sb[o];
    }
    if (lane < NEXPD) out[i * NEXPD + lane] = res;
}

// ---------------- launch ----------------
extern "C" void kernel_launch(void* const* d_in, const int* in_sizes, int n_in,
                              void* d_out, int out_size) {
    const float* te   = (const float*)d_in[0];
    const float* U    = (const float*)d_in[1];
    const float* R    = (const float*)d_in[2];
    const float* S    = (const float*)d_in[3];
    const float* tp_w = (const float*)d_in[4];
    const float* tp_b = (const float*)d_in[5];
    const float* q_w  = (const float*)d_in[6];
    const float* q_b  = (const float*)d_in[7];
    const float* k_w  = (const float*)d_in[8];
    const float* k_b  = (const float*)d_in[9];
    const float* v_w  = (const float*)d_in[10];
    const float* v_b  = (const float*)d_in[11];
    const float* wih  = (const float*)d_in[12];
    const float* whh  = (const float*)d_in[13];
    const float* bih  = (const float*)d_in[14];
    const float* bhh  = (const float*)d_in[15];
    const float* w1   = (const float*)d_in[16];
    const float* b1   = (const float*)d_in[17];
    const float* w2   = (const float*)d_in[18];
    const float* b2   = (const float*)d_in[19];
    float* out = (float*)d_out;

    k_pre<<<1, GDIM>>>(q_w, q_b, k_w, k_b, v_w, v_b, wih, bih);
    k_gemm1<<<dim3(NTOK / 128, PDIM / 128), 256>>>(te, tp_w, tp_b);
    k_attn<<<NTOK / 8, 256>>>(R, S);
    k_gru<<<NSEQ, GDIM>>>(U, whh, bhh);
    k_mlp1<<<dim3(NTOK / 128, 2), 256>>>(w1, b1);
    k_logits<<<NTOK / 8, 256>>>(w2, b2, out);
}

// round 7
// speedup vs baseline: 1.0693x; 1.0693x over previous
#include <cuda_runtime.h>

// Problem dims
#define BDIM 8
#define MDIM 4
#define TLEN 2048
#define EDIM 768
#define PDIM 256
#define KDIM 64
#define VDIM 64
#define HDIM 128
#define GDIM 384   /* 3*H */
#define CDIM 384   /* P + H */
#define HIDD 192
#define NEXPD 16
#define NTOK (BDIM*MDIM*TLEN)   /* 65536 */
#define NSEQ (BDIM*MDIM)        /* 32 */

// ---------------- scratch (device globals; no allocation allowed) ----------------
__device__ float g_proc[(size_t)NTOK * PDIM];   // 64 MB: relu(te @ tp_w^T + b)
__device__ float g_rs[(size_t)NTOK * 2];        // (rbar, sbar) per token
__device__ float g_rus[(size_t)NTOK * HDIM];    // GRU outputs
__device__ float g_hid[(size_t)NTOK * HIDD];    // MLP hidden
__device__ float g_pa[PDIM], g_pb[PDIM], g_pc[PDIM];
__device__ float g_wu[GDIM], g_wr[GDIM], g_wsv[GDIM], g_w0[GDIM];
__device__ float g_cabc[3];

__constant__ int c_others[4][3] = {{1,2,3},{0,2,3},{0,1,3},{0,1,2}};

// ---------------- f32x2 packed-FMA helpers (sm_100+/sm_103a) ----------------
__device__ __forceinline__ unsigned long long pack2(float lo, float hi) {
    unsigned long long r;
    asm("mov.b64 %0, {%1, %2};" : "=l"(r) : "f"(lo), "f"(hi));
    return r;
}
__device__ __forceinline__ float2 unpack2(unsigned long long v) {
    float2 r;
    asm("mov.b64 {%0, %1}, %2;" : "=f"(r.x), "=f"(r.y) : "l"(v));
    return r;
}
__device__ __forceinline__ void fma2(unsigned long long& d, unsigned long long a, unsigned long long b) {
    asm("fma.rn.f32x2 %0, %1, %2, %0;" : "+l"(d) : "l"(a), "l"(b));
}

__device__ __forceinline__ float sigmoidf_(float x) { return 1.f / (1.f + __expf(-x)); }
__device__ __forceinline__ float tanhf_(float x)    { return 1.f - 2.f / (__expf(2.f * x) + 1.f); }

// ---------------- precompute folded small weights ----------------
__global__ void k_pre(const float* __restrict__ qw, const float* __restrict__ qb,
                      const float* __restrict__ kw, const float* __restrict__ kb,
                      const float* __restrict__ vw, const float* __restrict__ vb,
                      const float* __restrict__ wih, const float* __restrict__ bih) {
    int j = threadIdx.x;
    if (j < PDIM) {
        float a = 0.f, b = 0.f, c = 0.f;
        for (int k = 0; k < KDIM; k++) {
            float q = qw[k * PDIM + j];
            a = fmaf(q, kw[2 * k], a);
            b = fmaf(q, kw[2 * k + 1], b);
            c = fmaf(q, kb[k], c);
        }
        g_pa[j] = a; g_pb[j] = b; g_pc[j] = c;
    }
    if (j < GDIM) {
        float wr = 0.f, ws = 0.f, w0 = 0.f;
        for (int v = 0; v < VDIM; v++) {
            float w = wih[j * (1 + VDIM) + 1 + v];
            wr = fmaf(w, vw[2 * v], wr);
            ws = fmaf(w, vw[2 * v + 1], ws);
            w0 = fmaf(w, vb[v], w0);
        }
        g_wu[j] = wih[j * (1 + VDIM)];
        g_wr[j] = wr; g_wsv[j] = ws; g_w0[j] = w0 + bih[j];
    }
    if (j == 0) {
        float a = 0.f, b = 0.f, c = 0.f;
        for (int k = 0; k < KDIM; k++) {
            a = fmaf(qb[k], kw[2 * k], a);
            b = fmaf(qb[k], kw[2 * k + 1], b);
            c = fmaf(qb[k], kb[k], c);
        }
        g_cabc[0] = a; g_cabc[1] = b; g_cabc[2] = c;
    }
}

// ---------------- GEMM1: g_proc = relu(te[NTOK,768] @ tp_w[256,768]^T + b) ----------------
// Tile 128x128x16, 256 threads, 8x8 microtile via f32x2.
__global__ __launch_bounds__(256, 2) void k_gemm1(const float* __restrict__ A,
                                                  const float* __restrict__ W,
                                                  const float* __restrict__ bias) {
    __shared__ float As[16][132];
    __shared__ float Ws[16][132];
    const int bi = blockIdx.x, bj = blockIdx.y;
    const int tid = threadIdx.x;
    const int tx = tid & 15, ty = tid >> 4;
    const int row0 = bi * 128, col0 = bj * 128;

    unsigned long long acc[8][4];
#pragma unroll
    for (int i = 0; i < 8; i++)
#pragma unroll
        for (int j = 0; j < 4; j++) acc[i][j] = 0ull;

    for (int ks = 0; ks < EDIM / 16; ks++) {
#pragma unroll
        for (int p = 0; p < 2; p++) {
            int idx = tid + p * 256;
            int r = idx >> 2;
            int kq = (idx & 3) << 2;
            float4 av = *(const float4*)&A[(size_t)(row0 + r) * EDIM + ks * 16 + kq];
            As[kq + 0][r] = av.x; As[kq + 1][r] = av.y; As[kq + 2][r] = av.z; As[kq + 3][r] = av.w;
            float4 wv = *(const float4*)&W[(size_t)(col0 + r) * EDIM + ks * 16 + kq];
            Ws[kq + 0][r] = wv.x; Ws[kq + 1][r] = wv.y; Ws[kq + 2][r] = wv.z; Ws[kq + 3][r] = wv.w;
        }
        __syncthreads();
#pragma unroll
        for (int kk = 0; kk < 16; kk++) {
            float4 a0 = *(const float4*)&As[kk][ty * 8];
            float4 a1 = *(const float4*)&As[kk][ty * 8 + 4];
            ulonglong2 wv0 = *(const ulonglong2*)&Ws[kk][tx * 8];
            ulonglong2 wv1 = *(const ulonglong2*)&Ws[kk][tx * 8 + 4];
            float ar[8] = {a0.x, a0.y, a0.z, a0.w, a1.x, a1.y, a1.z, a1.w};
#pragma unroll
            for (int i = 0; i < 8; i++) {
                unsigned long long ad = pack2(ar[i], ar[i]);
                fma2(acc[i][0], ad, wv0.x);
                fma2(acc[i][1], ad, wv0.y);
                fma2(acc[i][2], ad, wv1.x);
                fma2(acc[i][3], ad, wv1.y);
            }
        }
        __syncthreads();
    }
    const int crow = row0 + ty * 8;
    const int ccol = col0 + tx * 8;
    float bb[8];
#pragma unroll
    for (int j = 0; j < 8; j++) bb[j] = bias[ccol + j];
#pragma unroll
    for (int i = 0; i < 8; i++) {
        float2 p0 = unpack2(acc[i][0]), p1 = unpack2(acc[i][1]);
        float2 p2 = unpack2(acc[i][2]), p3 = unpack2(acc[i][3]);
        float4 v0 = make_float4(fmaxf(p0.x + bb[0], 0.f), fmaxf(p0.y + bb[1], 0.f),
                                fmaxf(p1.x + bb[2], 0.f), fmaxf(p1.y + bb[3], 0.f));
        float4 v1 = make_float4(fmaxf(p2.x + bb[4], 0.f), fmaxf(p2.y + bb[5], 0.f),
                                fmaxf(p3.x + bb[6], 0.f), fmaxf(p3.y + bb[7], 0.f));
        *(float4*)&g_proc[(size_t)(crow + i) * PDIM + ccol]     = v0;
        *(float4*)&g_proc[(size_t)(crow + i) * PDIM + ccol + 4] = v1;
    }
}

// ---------------- attention scalars: per token -> (rbar, sbar) ----------------
// warp per token; 8 warps per block.
__global__ __launch_bounds__(256) void k_attn(const float* __restrict__ R, const float* __restrict__ S) {
    __shared__ float spa[PDIM], spb[PDIM], spc[PDIM];
    int tid = threadIdx.x;
    if (tid < PDIM) { spa[tid] = g_pa[tid]; spb[tid] = g_pb[tid]; spc[tid] = g_pc[tid]; }
    __syncthreads();
    int warp = tid >> 5, lane = tid & 31;
    size_t i = (size_t)blockIdx.x * 8 + warp;
    const float* pr = &g_proc[i * PDIM];
    float a = 0.f, b = 0.f, c = 0.f;
#pragma unroll
    for (int q = 0; q < 8; q++) {
        int p = lane + 32 * q;
        float x = pr[p];
        a = fmaf(x, spa[p], a);
        b = fmaf(x, spb[p], b);
        c = fmaf(x, spc[p], c);
    }
#pragma unroll
    for (int d = 16; d > 0; d >>= 1) {
        a += __shfl_xor_sync(0xffffffffu, a, d);
        b += __shfl_xor_sync(0xffffffffu, b, d);
        c += __shfl_xor_sync(0xffffffffu, c, d);
    }
    if (lane == 0) {
        a += g_cabc[0]; b += g_cabc[1]; c += g_cabc[2];
        int t = (int)(i & (TLEN - 1));
        int bm = (int)(i >> 11);
        int m = bm & 3, bb = bm >> 2;
        float r[3], s[3], sc[3];
#pragma unroll
        for (int n = 0; n < 3; n++) {
            int o = c_others[m][n];
            size_t off = (((size_t)bb * 4 + m) * 4 + o) * TLEN + t;
            r[n] = R[off]; s[n] = S[off];
            sc[n] = (fmaf(a, r[n], fmaf(b, s[n], c))) * 0.125f;
        }
        float mx = fmaxf(sc[0], fmaxf(sc[1], sc[2]));
        float e0 = __expf(sc[0] - mx), e1 = __expf(sc[1] - mx), e2 = __expf(sc[2] - mx);
        float inv = __fdividef(1.f, e0 + e1 + e2);
        float rb = (e0 * r[0] + e1 * r[1] + e2 * r[2]) * inv;
        float sb = (e0 * s[0] + e1 * s[1] + e2 * s[2]) * inv;
        g_rs[i * 2 + 0] = rb;
        g_rs[i * 2 + 1] = sb;
    }
}

// ---------------- GRU: 32 CTAs (one per sequence), w_hh rows in registers ----------------
// v2: all per-step scalars preloaded to SMEM (no LDG in loop); 4 accumulator chains.
__global__ __launch_bounds__(GDIM, 1) void k_gru(const float* __restrict__ U,
                                                 const float* __restrict__ whh,
                                                 const float* __restrict__ bhh) {
    __shared__ float sh_h[HDIM];
    __shared__ float sh_g[2 * HDIM];
    __shared__ float sh_xn[HDIM];
    __shared__ float sh_hn[HDIM];
    __shared__ float sh_u[TLEN];       // 8 KB
    __shared__ float sh_rs[2 * TLEN];  // 16 KB
    const int j = threadIdx.x;
    const int s = blockIdx.x;

    // pack this row's w_hh into 64 f32x2 registers
    unsigned long long w2[64];
    {
        const float4* wrow = (const float4*)(whh + (size_t)j * HDIM);
#pragma unroll
        for (int q = 0; q < 32; q++) {
            float4 f = wrow[q];
            w2[2 * q]     = pack2(f.x, f.y);
            w2[2 * q + 1] = pack2(f.z, f.w);
        }
    }
    const float wu = g_wu[j], wr = g_wr[j], wsx = g_wsv[j], w0 = g_w0[j];
    const float bh = bhh[j];
    float hold = 0.f;
    if (j < HDIM) sh_h[j] = 0.f;

    // bulk-preload this sequence's scalar inputs (coalesced; removes all in-loop LDG)
    for (int i = j; i < TLEN; i += GDIM)       sh_u[i]  = U[(size_t)s * TLEN + i];
    for (int i = j; i < 2 * TLEN; i += GDIM)   sh_rs[i] = g_rs[(size_t)s * (2 * TLEN) + i];
    __syncthreads();
    const ulonglong2* sh_h2 = (const ulonglong2*)sh_h;
    float* rus_seq = &g_rus[(size_t)s * TLEN * HDIM];

    for (int t = 0; t < TLEN; t++) {
        float u = sh_u[t], rb = sh_rs[2 * t], sb = sh_rs[2 * t + 1];
        float xp = fmaf(u, wu, fmaf(rb, wr, fmaf(sb, wsx, w0)));
        // 4 independent accumulator chains (chain depth 16 each)
        unsigned long long a0 = 0ull, a1 = 0ull, a2 = 0ull, a3 = 0ull;
#pragma unroll
        for (int q = 0; q < 16; q++) {
            ulonglong2 h0 = sh_h2[2 * q];
            ulonglong2 h1 = sh_h2[2 * q + 1];
            fma2(a0, w2[4 * q + 0], h0.x);
            fma2(a1, w2[4 * q + 1], h0.y);
            fma2(a2, w2[4 * q + 2], h1.x);
            fma2(a3, w2[4 * q + 3], h1.y);
        }
        float2 f0 = unpack2(a0), f1 = unpack2(a1), f2 = unpack2(a2), f3 = unpack2(a3);
        float hp = bh + ((f0.x + f0.y) + (f1.x + f1.y)) + ((f2.x + f2.y) + (f3.x + f3.y));
        if (j < 2 * HDIM) sh_g[j] = xp + hp;
        else { sh_xn[j - 2 * HDIM] = xp; sh_hn[j - 2 * HDIM] = hp; }
        __syncthreads();
        if (j < HDIM) {
            float r = sigmoidf_(sh_g[j]);
            float z = sigmoidf_(sh_g[HDIM + j]);
            float n = tanhf_(fmaf(r, sh_hn[j], sh_xn[j]));
            hold = fmaf(z, hold - n, n);   // (1-z)*n + z*h
            sh_h[j] = hold;
            rus_seq[(size_t)t * HDIM + j] = hold;
        }
        __syncthreads();
    }
}

// ---------------- MLP1: g_hid = relu([proc|rus][NTOK,384] @ w1[192,384]^T + b1) ----------------
// Tile 128x96x16, 256 threads, 8x6 microtile via f32x2. grid.y = 2.
__global__ __launch_bounds__(256, 2) void k_mlp1(const float* __restrict__ W,
                                                 const float* __restrict__ bias) {
    __shared__ float As[16][132];
    __shared__ float Ws[16][100];
    const int bi = blockIdx.x, bj = blockIdx.y;
    const int tid = threadIdx.x;
    const int tx = tid & 15, ty = tid >> 4;
    const int row0 = bi * 128, col0 = bj * 96;

    unsigned long long acc[8][3];
#pragma unroll
    for (int i = 0; i < 8; i++)
#pragma unroll
        for (int j = 0; j < 3; j++) acc[i][j] = 0ull;

    for (int ks = 0; ks < CDIM / 16; ks++) {
#pragma unroll
        for (int p = 0; p < 2; p++) {
            int idx = tid + p * 256;
            int r = idx >> 2;
            int kq = (idx & 3) << 2;
            int k = ks * 16 + kq;
            float4 av;
            if (k < PDIM) av = *(const float4*)&g_proc[(size_t)(row0 + r) * PDIM + k];
            else          av = *(const float4*)&g_rus[(size_t)(row0 + r) * HDIM + (k - PDIM)];
            As[kq + 0][r] = av.x; As[kq + 1][r] = av.y; As[kq + 2][r] = av.z; As[kq + 3][r] = av.w;
        }
#pragma unroll
        for (int p = 0; p < 2; p++) {
            int idx = tid + p * 256;
            if (idx < 384) {
                int r = idx >> 2;
                int kq = (idx & 3) << 2;
                float4 wv = *(const float4*)&W[(size_t)(col0 + r) * CDIM + ks * 16 + kq];
                Ws[kq + 0][r] = wv.x; Ws[kq + 1][r] = wv.y; Ws[kq + 2][r] = wv.z; Ws[kq + 3][r] = wv.w;
            }
        }
        __syncthreads();
#pragma unroll
        for (int kk = 0; kk < 16; kk++) {
            float4 a0 = *(const float4*)&As[kk][ty * 8];
            float4 a1 = *(const float4*)&As[kk][ty * 8 + 4];
            const unsigned long long* wp = (const unsigned long long*)&Ws[kk][tx * 6];
            unsigned long long wv0 = wp[0], wv1 = wp[1], wv2 = wp[2];
            float ar[8] = {a0.x, a0.y, a0.z, a0.w, a1.x, a1.y, a1.z, a1.w};
#pragma unroll
            for (int i = 0; i < 8; i++) {
                unsigned long long ad = pack2(ar[i], ar[i]);
                fma2(acc[i][0], ad, wv0);
                fma2(acc[i][1], ad, wv1);
                fma2(acc[i][2], ad, wv2);
            }
        }
        __syncthreads();
    }
    const int crow = row0 + ty * 8;
    const int ccol = col0 + tx * 6;
    float bb[6];
#pragma unroll
    for (int j = 0; j < 6; j++) bb[j] = bias[ccol + j];
#pragma unroll
    for (int i = 0; i < 8; i++) {
        float2 p0 = unpack2(acc[i][0]), p1 = unpack2(acc[i][1]), p2 = unpack2(acc[i][2]);
        float2 v0 = make_float2(fmaxf(p0.x + bb[0], 0.f), fmaxf(p0.y + bb[1], 0.f));
        float2 v1 = make_float2(fmaxf(p1.x + bb[2], 0.f), fmaxf(p1.y + bb[3], 0.f));
        float2 v2 = make_float2(fmaxf(p2.x + bb[4], 0.f), fmaxf(p2.y + bb[5], 0.f));
        size_t base = (size_t)(crow + i) * HIDD + ccol;
        *(float2*)&g_hid[base]     = v0;
        *(float2*)&g_hid[base + 2] = v1;
        *(float2*)&g_hid[base + 4] = v2;
    }
}

// ---------------- logits: out = g_hid @ w2[16,192]^T + b2 ----------------
__global__ __launch_bounds__(256) void k_logits(const float* __restrict__ w2,
                                                const float* __restrict__ b2,
                                                float* __restrict__ out) {
    __shared__ float sw[NEXPD * HIDD];
    __shared__ float sb[NEXPD];
    int tid = threadIdx.x;
    for (int idx = tid; idx < NEXPD * HIDD; idx += 256) sw[idx] = w2[idx];
    if (tid < NEXPD) sb[tid] = b2[tid];
    __syncthreads();
    int warp = tid >> 5, lane = tid & 31;
    size_t i = (size_t)blockIdx.x * 8 + warp;
    float h[6];
#pragma unroll
    for (int q = 0; q < 6; q++) h[q] = g_hid[i * HIDD + lane + 32 * q];
    float res = 0.f;
#pragma unroll
    for (int o = 0; o < NEXPD; o++) {
        float p = 0.f;
#pragma unroll
        for (int q = 0; q < 6; q++) p = fmaf(h[q], sw[o * HIDD + lane + 32 * q], p);
#pragma unroll
        for (int d = 16; d > 0; d >>= 1) p += __shfl_xor_sync(0xffffffffu, p, d);
        if (lane == o) res = p + sb[o];
    }
    if (lane < NEXPD) out[i * NEXPD + lane] = res;
}

// ---------------- launch ----------------
extern "C" void kernel_launch(void* const* d_in, const int* in_sizes, int n_in,
                              void* d_out, int out_size) {
    const float* te   = (const float*)d_in[0];
    const float* U    = (const float*)d_in[1];
    const float* R    = (const float*)d_in[2];
    const float* S    = (const float*)d_in[3];
    const float* tp_w = (const float*)d_in[4];
    const float* tp_b = (const float*)d_in[5];
    const float* q_w  = (const float*)d_in[6];
    const float* q_b  = (const float*)d_in[7];
    const float* k_w  = (const float*)d_in[8];
    const float* k_b  = (const float*)d_in[9];
    const float* v_w  = (const float*)d_in[10];
    const float* v_b  = (const float*)d_in[11];
    const float* wih  = (const float*)d_in[12];
    const float* whh  = (const float*)d_in[13];
    const float* bih  = (const float*)d_in[14];
    const float* bhh  = (const float*)d_in[15];
    const float* w1   = (const float*)d_in[16];
    const float* b1   = (const float*)d_in[17];
    const float* w2   = (const float*)d_in[18];
    const float* b2   = (const float*)d_in[19];
    float* out = (float*)d_out;

    k_pre<<<1, GDIM>>>(q_w, q_b, k_w, k_b, v_w, v_b, wih, bih);
    k_gemm1<<<dim3(NTOK / 128, PDIM / 128), 256>>>(te, tp_w, tp_b);
    k_attn<<<NTOK / 8, 256>>>(R, S);
    k_gru<<<NSEQ, GDIM>>>(U, whh, bhh);
    k_mlp1<<<dim3(NTOK / 128, 2), 256>>>(w1, b1);
    k_logits<<<NTOK / 8, 256>>>(w2, b2, out);
}